// round 5
// baseline (speedup 1.0000x reference)
#include <cuda_runtime.h>

// AdaptivePooling2D: [16,225,225,256] f32 -> [16,7,7,256] f32 (channels_last)
// Windows: [32*o, 32*o+33) both dims, weight 1/1089 combined.
//
// Round-5: thread = (b, c4, grp, ox, half) sums an 8-column x ~16-row chunk
// of one window, one 4-float atomic scatter (plus one for the shared boundary
// column, tracked separately). vs round 4: per-thread work halved along rows
// -> 3248 CTAs (~2.2 residency fills) so CTA-completion spread is absorbed by
// later waves (round-4's 1.1-wave grid capped HBM at 6.95 TB/s; multi-wave
// grids reached 7.07). Traffic unchanged (851 MB), atomics ~2.0M scalar.

#define BB 16
#define HH 225
#define WW 225
#define C4 64            // 256 channels / 4 (float4)
#define OX 7
#define OY 7
#define NGRP 29          // 28 groups of 8 cols (w 0..223) + 1 group {224}

__global__ void __launch_bounds__(128)
pool_split_kernel(const float4* __restrict__ in, float* __restrict__ out)
{
    const int N = BB * C4 * NGRP * OX * 2; // 415,744 threads
    int idx = blockIdx.x * blockDim.x + threadIdx.x;
    if (idx >= N) return;

    const int c4 = idx & (C4 - 1);
    int t = idx >> 6;
    const int half = t & 1;
    t >>= 1;
    const int ox  = t % OX;
    t /= OX;
    const int grp = t % NGRP;
    const int b   = t / NGRP;

    const int w0 = grp * 8;
    const int h0 = ox * 32 + (half ? 17 : 0);
    const int nr = half ? 16 : 17;         // rows [0,17) / [17,33) of window

    // Primary column-window; w=224 (k=7) folds into window 6.
    const int k   = grp >> 2;
    const int oyP = (k < OY) ? k : (OY - 1);
    // First column of this group is a shared boundary column (w = 32k,
    // 1 <= k <= 6): its column-sum also feeds window k-1.
    const bool dual = ((grp & 3) == 0) && (grp >= 4) && (grp < 28);
    const int oyD = k - 1;

    const float4* __restrict__ p =
        in + ((size_t)(b * HH + h0) * WW + w0) * C4 + c4;
    const size_t rs = (size_t)WW * C4;     // row stride in float4 units

    float4 acc  = make_float4(0.f, 0.f, 0.f, 0.f);  // all 8 columns
    float4 acc0 = make_float4(0.f, 0.f, 0.f, 0.f);  // column j=0 only

    if (grp == NGRP - 1) {
        // Last group: single column w=224.
#pragma unroll 4
        for (int i = 0; i < nr; ++i) {
            float4 v = __ldg(p);
            p += rs;
            acc.x += v.x; acc.y += v.y; acc.z += v.z; acc.w += v.w;
        }
    } else {
#pragma unroll 1
        for (int i = 0; i < nr; ++i) {
            float4 v0 = __ldg(p + 0 * C4);
            float4 v1 = __ldg(p + 1 * C4);
            float4 v2 = __ldg(p + 2 * C4);
            float4 v3 = __ldg(p + 3 * C4);
            float4 v4 = __ldg(p + 4 * C4);
            float4 v5 = __ldg(p + 5 * C4);
            float4 v6 = __ldg(p + 6 * C4);
            float4 v7 = __ldg(p + 7 * C4);
            p += rs;

            acc0.x += v0.x; acc0.y += v0.y; acc0.z += v0.z; acc0.w += v0.w;

            acc.x += v0.x + v1.x + v2.x + v3.x + v4.x + v5.x + v6.x + v7.x;
            acc.y += v0.y + v1.y + v2.y + v3.y + v4.y + v5.y + v6.y + v7.y;
            acc.z += v0.z + v1.z + v2.z + v3.z + v4.z + v5.z + v6.z + v7.z;
            acc.w += v0.w + v1.w + v2.w + v3.w + v4.w + v5.w + v6.w + v7.w;
        }
    }

    const float s = 1.0f / (33.0f * 33.0f);

    float* o0 = out + ((((size_t)(b * OX + ox) * OY + oyP) * C4 + c4) << 2);
    atomicAdd(o0 + 0, acc.x * s);
    atomicAdd(o0 + 1, acc.y * s);
    atomicAdd(o0 + 2, acc.z * s);
    atomicAdd(o0 + 3, acc.w * s);

    if (dual) {
        float* o1 = out + ((((size_t)(b * OX + ox) * OY + oyD) * C4 + c4) << 2);
        atomicAdd(o1 + 0, acc0.x * s);
        atomicAdd(o1 + 1, acc0.y * s);
        atomicAdd(o1 + 2, acc0.z * s);
        atomicAdd(o1 + 3, acc0.w * s);
    }
}

extern "C" void kernel_launch(void* const* d_in, const int* in_sizes, int n_in,
                              void* d_out, int out_size)
{
    (void)in_sizes; (void)n_in;
    const float4* in = (const float4*)d_in[0];
    float* out = (float*)d_out;

    // Output is poisoned (0xAA) by the harness; atomics need zeros.
    cudaMemsetAsync(d_out, 0, (size_t)out_size * sizeof(float));

    const int n = BB * C4 * NGRP * OX * 2; // 415,744
    pool_split_kernel<<<(n + 127) / 128, 128>>>(in, out);
}

// round 6
// speedup vs baseline: 1.1186x; 1.1186x over previous
#include <cuda_runtime.h>

// AdaptivePooling2D: [16,225,225,256] f32 -> [16,7,7,256] f32 (channels_last)
// Windows: [32*o, 32*o+33) both dims, weight 1/1089 combined.
//
// Round-6: revert to round-4 loop structure (compile-time 33-row loop,
// unroll 2), but 4-column groups instead of 8 -> 408,576 threads so the chip
// is actually full (round 4 was only 0.69 of one wave; occ 62.7% was
// grid-limited). Rate model: HBM rate tracks resident-threads x batched
// loads/thread; this config gives ~100% occ x 8-16 in flight at ~32 regs.
// Traffic 851 MB, ~1.7M scalar atomics.

#define BB 16
#define HH 225
#define WW 225
#define C4 64            // 256 channels / 4 (float4)
#define OX 7
#define OY 7
#define NGRP 57          // 56 groups of 4 cols (w 0..223) + 1 group {224}

__global__ void __launch_bounds__(256)
pool_g4_kernel(const float4* __restrict__ in, float* __restrict__ out)
{
    const int N = BB * C4 * NGRP * OX;     // 408,576 threads
    int idx = blockIdx.x * blockDim.x + threadIdx.x;
    if (idx >= N) return;

    const int c4 = idx & (C4 - 1);
    int t = idx >> 6;
    const int ox  = t % OX;
    t /= OX;
    const int grp = t % NGRP;
    const int b   = t / NGRP;

    const int w0 = grp * 4;
    const int h0 = ox * 32;

    // Primary column-window; w=224 (k=7) folds into window 6.
    const int k   = grp >> 3;
    const int oyP = (k < OY) ? k : (OY - 1);
    // First column of group is a shared boundary column (w = 32k, 1<=k<=6):
    // its column-sum also feeds window k-1.
    const bool dual = ((grp & 7) == 0) && (grp >= 8) && (grp <= 48);
    const int oyD = k - 1;

    const float4* __restrict__ p =
        in + ((size_t)(b * HH + h0) * WW + w0) * C4 + c4;
    const size_t rs = (size_t)WW * C4;     // row stride in float4 units

    float4 acc  = make_float4(0.f, 0.f, 0.f, 0.f);  // all 4 columns
    float4 acc0 = make_float4(0.f, 0.f, 0.f, 0.f);  // column j=0 only

    if (grp == NGRP - 1) {
        // Last group: single column w=224.
#pragma unroll 11
        for (int i = 0; i < 33; ++i) {
            float4 v = __ldg(p);
            p += rs;
            acc.x += v.x; acc.y += v.y; acc.z += v.z; acc.w += v.w;
        }
    } else {
#pragma unroll 2
        for (int i = 0; i < 33; ++i) {
            float4 v0 = __ldg(p + 0 * C4);
            float4 v1 = __ldg(p + 1 * C4);
            float4 v2 = __ldg(p + 2 * C4);
            float4 v3 = __ldg(p + 3 * C4);
            p += rs;

            acc0.x += v0.x; acc0.y += v0.y; acc0.z += v0.z; acc0.w += v0.w;

            acc.x += v0.x + v1.x + v2.x + v3.x;
            acc.y += v0.y + v1.y + v2.y + v3.y;
            acc.z += v0.z + v1.z + v2.z + v3.z;
            acc.w += v0.w + v1.w + v2.w + v3.w;
        }
    }

    const float s = 1.0f / (33.0f * 33.0f);

    float* o0 = out + ((((size_t)(b * OX + ox) * OY + oyP) * C4 + c4) << 2);
    atomicAdd(o0 + 0, acc.x * s);
    atomicAdd(o0 + 1, acc.y * s);
    atomicAdd(o0 + 2, acc.z * s);
    atomicAdd(o0 + 3, acc.w * s);

    if (dual) {
        float* o1 = out + ((((size_t)(b * OX + ox) * OY + oyD) * C4 + c4) << 2);
        atomicAdd(o1 + 0, acc0.x * s);
        atomicAdd(o1 + 1, acc0.y * s);
        atomicAdd(o1 + 2, acc0.z * s);
        atomicAdd(o1 + 3, acc0.w * s);
    }
}

extern "C" void kernel_launch(void* const* d_in, const int* in_sizes, int n_in,
                              void* d_out, int out_size)
{
    (void)in_sizes; (void)n_in;
    const float4* in = (const float4*)d_in[0];
    float* out = (float*)d_out;

    // Output is poisoned (0xAA) by the harness; atomics need zeros.
    cudaMemsetAsync(d_out, 0, (size_t)out_size * sizeof(float));

    const int n = BB * C4 * NGRP * OX;     // 408,576
    pool_g4_kernel<<<(n + 255) / 256, 256>>>(in, out);
}